// round 7
// baseline (speedup 1.0000x reference)
#include <cuda_runtime.h>
#include <cuda_fp16.h>
#include <cstdint>

#define SDIM 512
#define FDIM 1024
#define KDIM 1024
#define MDIM 32768          // 64*512

// ---------------- device scratch ----------------
__device__ __half g_xh[(size_t)MDIM * KDIM];   // 64 MB
__device__ __half g_wh[(size_t)FDIM * KDIM];   // 2 MB
__device__ float  g_carry[64 * FDIM];          // carry h after chunk 0, [b][f]
__device__ int    g_flag[64 * 8];              // published flags [b][ntile]

__global__ void reset_flags_kernel() {
    int i = blockIdx.x * 256 + threadIdx.x;
    if (i < 64 * 8) g_flag[i] = 0;
}

// ---------------- conversion kernels ----------------
__global__ __launch_bounds__(256) void convert_x_kernel(const float* __restrict__ x) {
    size_t i = ((size_t)blockIdx.x * 256 + threadIdx.x) * 8;
    float4 a = *reinterpret_cast<const float4*>(x + i);
    float4 b = *reinterpret_cast<const float4*>(x + i + 4);
    __half2 h0 = __floats2half2_rn(a.x, a.y);
    __half2 h1 = __floats2half2_rn(a.z, a.w);
    __half2 h2 = __floats2half2_rn(b.x, b.y);
    __half2 h3 = __floats2half2_rn(b.z, b.w);
    uint4 u;
    u.x = *reinterpret_cast<unsigned*>(&h0);
    u.y = *reinterpret_cast<unsigned*>(&h1);
    u.z = *reinterpret_cast<unsigned*>(&h2);
    u.w = *reinterpret_cast<unsigned*>(&h3);
    *reinterpret_cast<uint4*>(g_xh + i) = u;
}

__global__ __launch_bounds__(256) void convert_w_kernel(const float* __restrict__ W) {
    size_t i = ((size_t)blockIdx.x * 256 + threadIdx.x) * 8;
    float4 a = *reinterpret_cast<const float4*>(W + i);
    float4 b = *reinterpret_cast<const float4*>(W + i + 4);
    __half2 h0 = __floats2half2_rn(a.x, a.y);
    __half2 h1 = __floats2half2_rn(a.z, a.w);
    __half2 h2 = __floats2half2_rn(b.x, b.y);
    __half2 h3 = __floats2half2_rn(b.z, b.w);
    uint4 u;
    u.x = *reinterpret_cast<unsigned*>(&h0);
    u.y = *reinterpret_cast<unsigned*>(&h1);
    u.z = *reinterpret_cast<unsigned*>(&h2);
    u.w = *reinterpret_cast<unsigned*>(&h3);
    *reinterpret_cast<uint4*>(g_wh + i) = u;
}

// ---------------- PTX helpers ----------------
__device__ __forceinline__ void cp_async16(void* smem, const void* gmem) {
    unsigned saddr = (unsigned)__cvta_generic_to_shared(smem);
    asm volatile("cp.async.cg.shared.global [%0], [%1], 16;\n" :: "r"(saddr), "l"(gmem));
}
__device__ __forceinline__ void cp_commit() { asm volatile("cp.async.commit_group;\n"); }
__device__ __forceinline__ void cp_wait1() { asm volatile("cp.async.wait_group 1;\n"); }

#define LDSM_X4(r0, r1, r2, r3, addr) \
    asm volatile("ldmatrix.sync.aligned.m8n8.x4.shared.b16 {%0,%1,%2,%3}, [%4];" \
                 : "=r"(r0), "=r"(r1), "=r"(r2), "=r"(r3) : "r"(addr))

__device__ __forceinline__ int ld_acquire(const int* p) {
    int v;
    asm volatile("ld.acquire.gpu.global.b32 %0, [%1];" : "=r"(v) : "l"(p) : "memory");
    return v;
}
__device__ __forceinline__ void st_release(int* p, int v) {
    asm volatile("st.release.gpu.global.b32 [%0], %1;" :: "l"(p), "r"(v) : "memory");
}

// ---------------- fused fp16 GEMM + EMA scan ----------------
// CTA 256x128, BK=64, 3 cp.async stages, 8 warps (4M x 2N), warp tile 64x64.
// 1 CTA/SM (reg-heavy). blockIdx.y = c*64 + b, c in {0,1} (s-chunks of 256).
#define BM 256
#define BN 128
#define BK 64
#define ROW_B 144                        // 64 halves + 16B pad
#define A_TILE_B (256 * ROW_B)           // 36864
#define B_TILE_B (128 * ROW_B)           // 18432
#define STAGE_B (A_TILE_B + B_TILE_B)    // 55296
#define STAGES 3
#define GEMM_SMEM (STAGES * STAGE_B)     // 165888 (>= 256*129*4 = 132096 epi)
#define EPI_STRIDE 129

__global__ __launch_bounds__(256, 1) void gemm_fused_kernel(
    float* __restrict__ hid, float* __restrict__ hk)
{
    extern __shared__ char smem[];
    const uint32_t smem_base = (uint32_t)__cvta_generic_to_shared(smem);

    const int tid   = threadIdx.x;
    const int lane  = tid & 31;
    const int warp  = tid >> 5;
    const int warpM = warp >> 1;   // 0..3 (64 rows)
    const int warpN = warp & 1;    // 0..1 (64 cols)

    const int ntile = blockIdx.x;          // 0..7
    const int b     = blockIdx.y & 63;     // batch
    const int c     = blockIdx.y >> 6;     // s-chunk of 256 (outermost)
    const int m0    = b * SDIM + c * 256;  // row in flattened [B*S]
    const int n0    = ntile * BN;

    float acc[4][4][2][4];                 // [mt][nt16][n8][4]
    #pragma unroll
    for (int i = 0; i < 4; i++)
        #pragma unroll
        for (int j = 0; j < 4; j++)
            #pragma unroll
            for (int q = 0; q < 2; q++)
                #pragma unroll
                for (int k = 0; k < 4; k++)
                    acc[i][j][q][k] = 0.0f;

    auto load_stage = [&](int slot, int k0) {
        char* sa = smem + slot * STAGE_B;
        char* sb = sa + A_TILE_B;
        #pragma unroll
        for (int i = 0; i < 8; i++) {        // A: 2048 16B chunks
            int l = tid + i * 256;
            int row = l >> 3, cc = l & 7;
            cp_async16(sa + row * ROW_B + cc * 16,
                       g_xh + (size_t)(m0 + row) * KDIM + k0 + cc * 8);
        }
        #pragma unroll
        for (int i = 0; i < 4; i++) {        // B: 1024 16B chunks
            int l = tid + i * 256;
            int row = l >> 3, cc = l & 7;
            cp_async16(sb + row * ROW_B + cc * 16,
                       g_wh + (size_t)(n0 + row) * KDIM + k0 + cc * 8);
        }
    };

    load_stage(0, 0);  cp_commit();
    load_stage(1, BK); cp_commit();

    const int a_row = warpM * 64 + (lane & 15);
    const int a_kc  = (lane >> 4) << 3;
    const int b_rw  = warpN * 64 + (lane & 7) + ((lane >> 4) << 3);   // + nt*16
    const int b_kc  = ((lane >> 3) & 1) << 3;

    const int KTILES = KDIM / BK;   // 16
    for (int kt = 0; kt < KTILES; kt++) {
        cp_wait1();
        __syncthreads();

        if (kt + 2 < KTILES) load_stage((kt + 2) % STAGES, (kt + 2) * BK);
        cp_commit();

        const uint32_t sa = smem_base + (kt % STAGES) * STAGE_B;
        const uint32_t sb = sa + A_TILE_B;

        #pragma unroll
        for (int kk = 0; kk < 4; kk++) {
            const int kb = kk * 16;   // halves
            uint32_t a[4][4];
            #pragma unroll
            for (int mt = 0; mt < 4; mt++) {
                uint32_t addr = sa + (a_row + mt * 16) * ROW_B + (kb + a_kc) * 2;
                LDSM_X4(a[mt][0], a[mt][1], a[mt][2], a[mt][3], addr);
            }
            uint32_t bf[4][4];
            #pragma unroll
            for (int nt = 0; nt < 4; nt++) {
                uint32_t addr = sb + (b_rw + nt * 16) * ROW_B + (kb + b_kc) * 2;
                LDSM_X4(bf[nt][0], bf[nt][1], bf[nt][2], bf[nt][3], addr);
            }
            #pragma unroll
            for (int mt = 0; mt < 4; mt++) {
                #pragma unroll
                for (int nt = 0; nt < 4; nt++) {
                    asm volatile(
                        "mma.sync.aligned.m16n8k16.row.col.f32.f16.f16.f32 "
                        "{%0,%1,%2,%3}, {%4,%5,%6,%7}, {%8,%9}, {%0,%1,%2,%3};\n"
                        : "+f"(acc[mt][nt][0][0]), "+f"(acc[mt][nt][0][1]),
                          "+f"(acc[mt][nt][0][2]), "+f"(acc[mt][nt][0][3])
                        : "r"(a[mt][0]), "r"(a[mt][1]), "r"(a[mt][2]), "r"(a[mt][3]),
                          "r"(bf[nt][0]), "r"(bf[nt][1]));
                    asm volatile(
                        "mma.sync.aligned.m16n8k16.row.col.f32.f16.f16.f32 "
                        "{%0,%1,%2,%3}, {%4,%5,%6,%7}, {%8,%9}, {%0,%1,%2,%3};\n"
                        : "+f"(acc[mt][nt][1][0]), "+f"(acc[mt][nt][1][1]),
                          "+f"(acc[mt][nt][1][2]), "+f"(acc[mt][nt][1][3])
                        : "r"(a[mt][0]), "r"(a[mt][1]), "r"(a[mt][2]), "r"(a[mt][3]),
                          "r"(bf[nt][2]), "r"(bf[nt][3]));
                }
            }
        }
    }
    __syncthreads();   // all LDSM reads done before epilogue reuses smem

    // ---------------- fused epilogue: stage C tile, scan s-chunk of 256 ----------------
    float* ctile = reinterpret_cast<float*>(smem);   // [256][EPI_STRIDE]

    #pragma unroll
    for (int mt = 0; mt < 4; mt++) {
        #pragma unroll
        for (int nt = 0; nt < 4; nt++) {
            #pragma unroll
            for (int q = 0; q < 2; q++) {
                int r  = warpM * 64 + mt * 16 + (lane >> 2);
                int cc = warpN * 64 + nt * 16 + q * 8 + (lane & 3) * 2;
                ctile[r * EPI_STRIDE + cc]           = acc[mt][nt][q][0];
                ctile[r * EPI_STRIDE + cc + 1]       = acc[mt][nt][q][1];
                ctile[(r + 8) * EPI_STRIDE + cc]     = acc[mt][nt][q][2];
                ctile[(r + 8) * EPI_STRIDE + cc + 1] = acc[mt][nt][q][3];
            }
        }
    }

    if (c > 0 && tid == 0) {
        const int* flag = &g_flag[b * 8 + ntile];
        while (ld_acquire(flag) == 0) { }
    }
    __syncthreads();

    if (tid < 128) {
        const int f = n0 + tid;
        float h = (c > 0) ? g_carry[b * FDIM + f] : 0.0f;
        float* orow = hid + (size_t)(b * SDIM + c * 256) * FDIM + f;
        #pragma unroll 4
        for (int s = 0; s < 256; s++) {
            h = 0.5f * (h + ctile[s * EPI_STRIDE + tid]);
            __stcs(orow + (size_t)s * FDIM, h);
        }
        if (c == 0) g_carry[b * FDIM + f] = h;
        else        hk[b * FDIM + f] = h;
    }
    __syncthreads();
    if (tid == 0 && c == 0) {
        __threadfence();
        st_release(&g_flag[b * 8 + ntile], 1);
    }
}

extern "C" void kernel_launch(void* const* d_in, const int* in_sizes, int n_in,
                              void* d_out, int out_size) {
    const float* x = (const float*)d_in[0];   // [64, 512, 1024]
    const float* W = (const float*)d_in[1];   // [1024, 1024]
    float* out = (float*)d_out;
    float* hk  = out;                          // [64, 1024]
    float* hid = out + (size_t)64 * FDIM;      // [64, 512, 1024]

    cudaFuncSetAttribute(gemm_fused_kernel,
                         cudaFuncAttributeMaxDynamicSharedMemorySize, GEMM_SMEM);

    reset_flags_kernel<<<2, 256>>>();
    convert_w_kernel<<<512, 256>>>(W);
    convert_x_kernel<<<16384, 256>>>(x);
    dim3 grid(FDIM / BN, 128);                 // y = c*64 + b, c in {0,1}
    gemm_fused_kernel<<<grid, 256, GEMM_SMEM>>>(hid, hk);
}

// round 8
// speedup vs baseline: 1.2109x; 1.2109x over previous
#include <cuda_runtime.h>
#include <cuda_fp16.h>
#include <cstdint>

#define SDIM 512
#define FDIM 1024
#define KDIM 1024
#define MDIM 32768          // 64*512

// ---------------- device scratch ----------------
__device__ __half g_xh[(size_t)MDIM * KDIM];   // 64 MB
__device__ __half g_wh[(size_t)FDIM * KDIM];   // 2 MB
__device__ float  g_carry[64 * 4 * FDIM];      // carry h after chunk c, [b][c][f]
__device__ int    g_flag[64 * 4 * 8];          // published flags [b][c][ntile]

// ---------------- merged prep: reset flags + convert W + convert x ----------------
__global__ __launch_bounds__(256) void prep_kernel(const float* __restrict__ x,
                                                   const float* __restrict__ W) {
    const int bid = blockIdx.x;
    if (bid < 16384) {                      // convert x: 16384 blocks
        size_t i = ((size_t)bid * 256 + threadIdx.x) * 8;
        float4 a = *reinterpret_cast<const float4*>(x + i);
        float4 b = *reinterpret_cast<const float4*>(x + i + 4);
        __half2 h0 = __floats2half2_rn(a.x, a.y);
        __half2 h1 = __floats2half2_rn(a.z, a.w);
        __half2 h2 = __floats2half2_rn(b.x, b.y);
        __half2 h3 = __floats2half2_rn(b.z, b.w);
        uint4 u;
        u.x = *reinterpret_cast<unsigned*>(&h0);
        u.y = *reinterpret_cast<unsigned*>(&h1);
        u.z = *reinterpret_cast<unsigned*>(&h2);
        u.w = *reinterpret_cast<unsigned*>(&h3);
        *reinterpret_cast<uint4*>(g_xh + i) = u;
    } else if (bid < 16896) {               // convert W: 512 blocks
        size_t i = ((size_t)(bid - 16384) * 256 + threadIdx.x) * 8;
        float4 a = *reinterpret_cast<const float4*>(W + i);
        float4 b = *reinterpret_cast<const float4*>(W + i + 4);
        __half2 h0 = __floats2half2_rn(a.x, a.y);
        __half2 h1 = __floats2half2_rn(a.z, a.w);
        __half2 h2 = __floats2half2_rn(b.x, b.y);
        __half2 h3 = __floats2half2_rn(b.z, b.w);
        uint4 u;
        u.x = *reinterpret_cast<unsigned*>(&h0);
        u.y = *reinterpret_cast<unsigned*>(&h1);
        u.z = *reinterpret_cast<unsigned*>(&h2);
        u.w = *reinterpret_cast<unsigned*>(&h3);
        *reinterpret_cast<uint4*>(g_wh + i) = u;
    } else {                                // reset flags: 1 block
        int i = threadIdx.x;
        for (; i < 64 * 4 * 8; i += 256) g_flag[i] = 0;
    }
}

// ---------------- PTX helpers ----------------
__device__ __forceinline__ void cp_async16(void* smem, const void* gmem) {
    unsigned saddr = (unsigned)__cvta_generic_to_shared(smem);
    asm volatile("cp.async.cg.shared.global [%0], [%1], 16;\n" :: "r"(saddr), "l"(gmem));
}
__device__ __forceinline__ void cp_commit() { asm volatile("cp.async.commit_group;\n"); }
__device__ __forceinline__ void cp_wait1() { asm volatile("cp.async.wait_group 1;\n"); }

#define LDSM_X4(r0, r1, r2, r3, addr) \
    asm volatile("ldmatrix.sync.aligned.m8n8.x4.shared.b16 {%0,%1,%2,%3}, [%4];" \
                 : "=r"(r0), "=r"(r1), "=r"(r2), "=r"(r3) : "r"(addr))

__device__ __forceinline__ int ld_acquire(const int* p) {
    int v;
    asm volatile("ld.acquire.gpu.global.b32 %0, [%1];" : "=r"(v) : "l"(p) : "memory");
    return v;
}
__device__ __forceinline__ void st_release(int* p, int v) {
    asm volatile("st.release.gpu.global.b32 [%0], %1;" :: "l"(p), "r"(v) : "memory");
}

// ---------------- fused fp16 GEMM + EMA scan (R6 config, smoothed loads) ----------------
// CTA 128x128, BK=64, 3 cp.async stages, 8 warps (2M x 4N), warp tile 64x32, 2 CTA/SM.
// blockIdx.y = c*64 + b (c outermost, dependency distance 512 bids).
#define BM 128
#define BN 128
#define BK 64
#define ROW_B 144                       // 64 halves + 16B pad
#define TILE_B (128 * ROW_B)            // 18432
#define STAGE_B (2 * TILE_B)            // 36864
#define STAGES 3
#define GEMM_SMEM (STAGES * STAGE_B)    // 110592
#define EPI_STRIDE 129

__global__ __launch_bounds__(256, 2) void gemm_fused_kernel(
    float* __restrict__ hid, float* __restrict__ hk)
{
    extern __shared__ char smem[];
    const uint32_t smem_base = (uint32_t)__cvta_generic_to_shared(smem);

    const int tid   = threadIdx.x;
    const int lane  = tid & 31;
    const int warp  = tid >> 5;
    const int warpM = warp >> 2;   // 0..1 (64 rows)
    const int warpN = warp & 3;    // 0..3 (32 cols)

    const int ntile = blockIdx.x;          // 0..7
    const int b     = blockIdx.y & 63;     // batch
    const int c     = blockIdx.y >> 6;     // s-chunk (outermost)
    const int m0    = (b * 4 + c) * BM;
    const int n0    = ntile * BN;

    float acc[4][4][4];
    #pragma unroll
    for (int i = 0; i < 4; i++)
        #pragma unroll
        for (int j = 0; j < 4; j++)
            #pragma unroll
            for (int k = 0; k < 4; k++)
                acc[i][j][k] = 0.0f;

    // per-thread load coords (8 rows of 8 chunks per tile half)
    const int ld_row = tid >> 3;           // 0..31 (+32*i)
    const int ld_c   = tid & 7;

    auto load_A = [&](int slot, int k0) {
        char* sa = smem + slot * STAGE_B;
        #pragma unroll
        for (int i = 0; i < 4; i++) {
            int row = ld_row + i * 32;
            cp_async16(sa + row * ROW_B + ld_c * 16,
                       g_xh + (size_t)(m0 + row) * KDIM + k0 + ld_c * 8);
        }
    };
    auto load_B = [&](int slot, int k0) {
        char* sb = smem + slot * STAGE_B + TILE_B;
        #pragma unroll
        for (int i = 0; i < 4; i++) {
            int row = ld_row + i * 32;
            cp_async16(sb + row * ROW_B + ld_c * 16,
                       g_wh + (size_t)(n0 + row) * KDIM + k0 + ld_c * 8);
        }
    };

    load_A(0, 0);  load_B(0, 0);  cp_commit();
    load_A(1, BK); load_B(1, BK); cp_commit();

    const int a_row = warpM * 64 + (lane & 15);
    const int a_kc  = (lane >> 4) << 3;
    const int b_row = warpN * 32 + (lane & 7) + ((lane >> 4) << 3);
    const int b_kc  = ((lane >> 3) & 1) << 3;

    auto do_kk = [&](uint32_t sa, uint32_t sb, int kb) {
        uint32_t a[4][4];
        #pragma unroll
        for (int mt = 0; mt < 4; mt++) {
            uint32_t addr = sa + (a_row + mt * 16) * ROW_B + (kb + a_kc) * 2;
            LDSM_X4(a[mt][0], a[mt][1], a[mt][2], a[mt][3], addr);
        }
        #pragma unroll
        for (int p = 0; p < 2; p++) {
            uint32_t b0, b1, b2, b3;
            uint32_t addr = sb + (b_row + p * 16) * ROW_B + (kb + b_kc) * 2;
            LDSM_X4(b0, b1, b2, b3, addr);
            #pragma unroll
            for (int mt = 0; mt < 4; mt++) {
                asm volatile(
                    "mma.sync.aligned.m16n8k16.row.col.f32.f16.f16.f32 "
                    "{%0,%1,%2,%3}, {%4,%5,%6,%7}, {%8,%9}, {%0,%1,%2,%3};\n"
                    : "+f"(acc[mt][2*p][0]), "+f"(acc[mt][2*p][1]),
                      "+f"(acc[mt][2*p][2]), "+f"(acc[mt][2*p][3])
                    : "r"(a[mt][0]), "r"(a[mt][1]), "r"(a[mt][2]), "r"(a[mt][3]),
                      "r"(b0), "r"(b1));
                asm volatile(
                    "mma.sync.aligned.m16n8k16.row.col.f32.f16.f16.f32 "
                    "{%0,%1,%2,%3}, {%4,%5,%6,%7}, {%8,%9}, {%0,%1,%2,%3};\n"
                    : "+f"(acc[mt][2*p+1][0]), "+f"(acc[mt][2*p+1][1]),
                      "+f"(acc[mt][2*p+1][2]), "+f"(acc[mt][2*p+1][3])
                    : "r"(a[mt][0]), "r"(a[mt][1]), "r"(a[mt][2]), "r"(a[mt][3]),
                      "r"(b2), "r"(b3));
            }
        }
    };

    const int KTILES = KDIM / BK;   // 16
    for (int kt = 0; kt < KTILES; kt++) {
        cp_wait1();
        __syncthreads();

        const uint32_t sa = smem_base + (kt % STAGES) * STAGE_B;
        const uint32_t sb = sa + TILE_B;
        const int nk = kt + 2;
        const int nslot = nk % STAGES;
        const bool do_load = nk < KTILES;

        do_kk(sa, sb, 0);
        if (do_load) load_A(nslot, nk * BK);   // interleave: A loads after kk0
        do_kk(sa, sb, 16);
        if (do_load) load_B(nslot, nk * BK);   // B loads after kk1
        do_kk(sa, sb, 32);
        cp_commit();
        do_kk(sa, sb, 48);
    }
    __syncthreads();   // all LDSM reads done before epilogue reuses smem

    // ---------------- fused epilogue: stage C tile, scan s-chunk ----------------
    float* ctile = reinterpret_cast<float*>(smem);   // [128][EPI_STRIDE]

    #pragma unroll
    for (int mt = 0; mt < 4; mt++) {
        #pragma unroll
        for (int nt = 0; nt < 4; nt++) {
            int r = warpM * 64 + mt * 16 + (lane >> 2);
            int cc = warpN * 32 + nt * 8 + (lane & 3) * 2;
            ctile[r * EPI_STRIDE + cc]           = acc[mt][nt][0];
            ctile[r * EPI_STRIDE + cc + 1]       = acc[mt][nt][1];
            ctile[(r + 8) * EPI_STRIDE + cc]     = acc[mt][nt][2];
            ctile[(r + 8) * EPI_STRIDE + cc + 1] = acc[mt][nt][3];
        }
    }

    if (c > 0 && tid == 0) {
        const int* flag = &g_flag[(b * 4 + (c - 1)) * 8 + ntile];
        while (ld_acquire(flag) == 0) { }
    }
    __syncthreads();

    if (tid < 128) {
        const int f = n0 + tid;
        float h = (c > 0) ? g_carry[(b * 4 + (c - 1)) * FDIM + f] : 0.0f;
        float* orow = hid + (size_t)(b * SDIM + c * 128) * FDIM + f;
        #pragma unroll 4
        for (int s = 0; s < 128; s++) {
            h = 0.5f * (h + ctile[s * EPI_STRIDE + tid]);
            __stcs(orow + (size_t)s * FDIM, h);
        }
        if (c < 3) g_carry[(b * 4 + c) * FDIM + f] = h;
        else       hk[b * FDIM + f] = h;
    }
    __syncthreads();
    if (tid == 0 && c < 3) {
        __threadfence();
        st_release(&g_flag[(b * 4 + c) * 8 + ntile], 1);
    }
}

extern "C" void kernel_launch(void* const* d_in, const int* in_sizes, int n_in,
                              void* d_out, int out_size) {
    const float* x = (const float*)d_in[0];   // [64, 512, 1024]
    const float* W = (const float*)d_in[1];   // [1024, 1024]
    float* out = (float*)d_out;
    float* hk  = out;                          // [64, 1024]
    float* hid = out + (size_t)64 * FDIM;      // [64, 512, 1024]

    cudaFuncSetAttribute(gemm_fused_kernel,
                         cudaFuncAttributeMaxDynamicSharedMemorySize, GEMM_SMEM);

    prep_kernel<<<16897, 256>>>(x, W);
    dim3 grid(FDIM / BN, 256);                 // y = c*64 + b
    gemm_fused_kernel<<<grid, 256, GEMM_SMEM>>>(hid, hk);
}